// round 2
// baseline (speedup 1.0000x reference)
#include <cuda_runtime.h>
#include <cstdint>

// Problem constants
#define TOTAL_N 341
#define BATCH   64
#define DMODEL  768
#define NHEADS  12
#define HDIM    64
#define MTOK    (BATCH * TOTAL_N)   // 21824

// Scratch (device globals: allocation-free)
__device__ float g_qkv[(size_t)MTOK * 3 * DMODEL];  // [M, 2304]
__device__ float g_att[(size_t)MTOK * DMODEL];      // [M, 768]

// ---------------------------------------------------------------------------
// helpers
// ---------------------------------------------------------------------------
__device__ __forceinline__ float to_tf32(float x) {
    uint32_t y;
    asm("cvt.rna.tf32.f32 %0, %1;" : "=r"(y) : "f"(x));
    return __uint_as_float(y);
}

__device__ __forceinline__ void mma_tf32(float* c, const uint32_t* a, uint32_t b0, uint32_t b1) {
    asm volatile(
        "mma.sync.aligned.m16n8k8.row.col.f32.tf32.tf32.f32 "
        "{%0,%1,%2,%3}, {%4,%5,%6,%7}, {%8,%9}, {%0,%1,%2,%3};\n"
        : "+f"(c[0]), "+f"(c[1]), "+f"(c[2]), "+f"(c[3])
        : "r"(a[0]), "r"(a[1]), "r"(a[2]), "r"(a[3]), "r"(b0), "r"(b1));
}

__device__ __forceinline__ uint32_t fau(float x) { return __float_as_uint(x); }

// Allowed key prefix length for query index q (cum = [0,1,5,21,85,341])
__device__ __forceinline__ int limit_of(int q) {
    if (q == 0)  return 341;   // CLS attends everywhere
    if (q < 5)   return 5;
    if (q < 21)  return 21;
    if (q < 85)  return 85;
    return 341;
}

// ---------------------------------------------------------------------------
// GEMM: C[M,N] = A[M,K] @ W[N,K]^T + bias[N]    (tf32 mma, 128x128x32 tiles)
// ---------------------------------------------------------------------------
#define GS 36   // smem row stride (pad 32 -> 36 for conflict-free frag reads)

template <int N, int K>
__device__ __forceinline__ void gemm_body(const float* __restrict__ A,
                                          const float* __restrict__ W,
                                          const float* __restrict__ bias,
                                          float* __restrict__ C, int M) {
    __shared__ float As[128 * GS];
    __shared__ float Bs[128 * GS];

    const int tid  = threadIdx.x;
    const int lane = tid & 31;
    const int warp = tid >> 5;
    const int g    = lane >> 2;   // group id (row within m16 / col within n8)
    const int t    = lane & 3;    // thread in group (k index)
    const int wm   = warp >> 1;   // 0..3
    const int wn   = warp & 1;    // 0..1
    const int bm   = blockIdx.y * 128;
    const int bn   = blockIdx.x * 128;

    float acc[2][8][4];
#pragma unroll
    for (int mi = 0; mi < 2; mi++)
#pragma unroll
        for (int ni = 0; ni < 8; ni++)
#pragma unroll
            for (int j = 0; j < 4; j++) acc[mi][ni][j] = 0.f;

    for (int kb = 0; kb < K; kb += 32) {
        // stage A and W tiles (convert to tf32-rounded values here)
#pragma unroll
        for (int i = 0; i < 4; i++) {
            int idx = tid + i * 256;
            int row = idx >> 3;
            int c4  = (idx & 7) << 2;

            float4 va = make_float4(0.f, 0.f, 0.f, 0.f);
            int gr = bm + row;
            if (gr < M) va = *(const float4*)(A + (size_t)gr * K + kb + c4);
            va.x = to_tf32(va.x); va.y = to_tf32(va.y);
            va.z = to_tf32(va.z); va.w = to_tf32(va.w);
            *(float4*)(As + row * GS + c4) = va;

            float4 vb = make_float4(0.f, 0.f, 0.f, 0.f);
            int gc = bn + row;
            if (gc < N) vb = *(const float4*)(W + (size_t)gc * K + kb + c4);
            vb.x = to_tf32(vb.x); vb.y = to_tf32(vb.y);
            vb.z = to_tf32(vb.z); vb.w = to_tf32(vb.w);
            *(float4*)(Bs + row * GS + c4) = vb;
        }
        __syncthreads();

#pragma unroll
        for (int ks = 0; ks < 4; ks++) {
            int k0 = ks * 8;
            uint32_t af[2][4];
#pragma unroll
            for (int mi = 0; mi < 2; mi++) {
                const float* p = As + (wm * 32 + mi * 16 + g) * GS + k0 + t;
                af[mi][0] = fau(p[0]);
                af[mi][1] = fau(p[8 * GS]);
                af[mi][2] = fau(p[4]);
                af[mi][3] = fau(p[8 * GS + 4]);
            }
#pragma unroll
            for (int ni = 0; ni < 8; ni++) {
                const float* p = Bs + (wn * 64 + ni * 8 + g) * GS + k0 + t;
                uint32_t b0 = fau(p[0]);
                uint32_t b1 = fau(p[4]);
#pragma unroll
                for (int mi = 0; mi < 2; mi++) mma_tf32(acc[mi][ni], af[mi], b0, b1);
            }
        }
        __syncthreads();
    }

    // epilogue: + bias, store
#pragma unroll
    for (int mi = 0; mi < 2; mi++) {
        int r0 = bm + wm * 32 + mi * 16 + g;
        int r1 = r0 + 8;
#pragma unroll
        for (int ni = 0; ni < 8; ni++) {
            int col = bn + wn * 64 + ni * 8 + 2 * t;
            float b0 = bias[col], b1 = bias[col + 1];
            if (r0 < M) {
                float2 v = make_float2(acc[mi][ni][0] + b0, acc[mi][ni][1] + b1);
                *(float2*)(C + (size_t)r0 * N + col) = v;
            }
            if (r1 < M) {
                float2 v = make_float2(acc[mi][ni][2] + b0, acc[mi][ni][3] + b1);
                *(float2*)(C + (size_t)r1 * N + col) = v;
            }
        }
    }
}

__global__ __launch_bounds__(256) void gemm_qkv_kernel(const float* __restrict__ x,
                                                       const float* __restrict__ w,
                                                       const float* __restrict__ bias) {
    gemm_body<3 * DMODEL, DMODEL>(x, w, bias, g_qkv, MTOK);
}

__global__ __launch_bounds__(256) void gemm_proj_kernel(const float* __restrict__ w,
                                                        const float* __restrict__ bias,
                                                        float* __restrict__ out) {
    gemm_body<DMODEL, DMODEL>(g_att, w, bias, out, MTOK);
}

// ---------------------------------------------------------------------------
// Fused flash attention: one CTA = (q-tile of 64 rows, head, batch)
// 4 warps x 16 q-rows. tf32 mma for S=Q K^T and O += P V.
// ---------------------------------------------------------------------------
#define KS_STRIDE 68   // [n][k]-read pattern conflict-free (stride % 32 == 4)
#define VS_STRIDE 72   // [k][n]-read pattern conflict-free (stride % 32 == 8)

__global__ __launch_bounds__(128) void attn_kernel() {
    extern __shared__ float sm[];
    float* Ks = sm;                      // 64 x 68
    float* Ps = sm + 64 * KS_STRIDE;     // 64 x 68 (also Q staging)
    float* Vs = sm + 2 * 64 * KS_STRIDE; // 64 x 72

    const int tid  = threadIdx.x;
    const int lane = tid & 31;
    const int warp = tid >> 5;
    const int g    = lane >> 2;
    const int t    = lane & 3;

    const int q0 = blockIdx.x * 64;
    const int h  = blockIdx.y;
    const int b  = blockIdx.z;
    const size_t rowbase = (size_t)b * TOTAL_N;
    const int hoff = h * HDIM;

    // stage Q tile into Ps, then lift fragments into registers
#pragma unroll
    for (int i = 0; i < 8; i++) {
        int idx = tid + i * 128;
        int row = idx >> 4;
        int c4  = (idx & 15) << 2;
        float4 v = make_float4(0.f, 0.f, 0.f, 0.f);
        int qi = q0 + row;
        if (qi < TOTAL_N) v = *(const float4*)(g_qkv + (rowbase + qi) * 2304 + hoff + c4);
        v.x = to_tf32(v.x); v.y = to_tf32(v.y); v.z = to_tf32(v.z); v.w = to_tf32(v.w);
        *(float4*)(Ps + row * KS_STRIDE + c4) = v;
    }
    __syncthreads();

    const int prow = warp * 16 + g;
    uint32_t qf[8][4];
#pragma unroll
    for (int d8 = 0; d8 < 8; d8++) {
        const float* p = Ps + prow * KS_STRIDE + d8 * 8 + t;
        qf[d8][0] = fau(p[0]);
        qf[d8][1] = fau(p[8 * KS_STRIDE]);
        qf[d8][2] = fau(p[4]);
        qf[d8][3] = fau(p[8 * KS_STRIDE + 4]);
    }
    __syncthreads();  // Ps gets reused for P

    float o[8][4];
#pragma unroll
    for (int d8 = 0; d8 < 8; d8++)
#pragma unroll
        for (int j = 0; j < 4; j++) o[d8][j] = 0.f;

    float m0 = -1e30f, m1 = -1e30f, l0 = 0.f, l1 = 0.f;
    const int lim0 = limit_of(q0 + prow);
    const int lim1 = limit_of(q0 + prow + 8);

    for (int kt = 0; kt < 6; kt++) {
        int key0 = kt * 64;
        // load K,V tiles
#pragma unroll
        for (int i = 0; i < 8; i++) {
            int idx = tid + i * 128;
            int row = idx >> 4;
            int c4  = (idx & 15) << 2;
            float4 kv = make_float4(0.f, 0.f, 0.f, 0.f);
            float4 vv = make_float4(0.f, 0.f, 0.f, 0.f);
            int key = key0 + row;
            if (key < TOTAL_N) {
                const float* base = g_qkv + (rowbase + key) * 2304 + hoff;
                kv = *(const float4*)(base + DMODEL + c4);
                vv = *(const float4*)(base + 2 * DMODEL + c4);
            }
            kv.x = to_tf32(kv.x); kv.y = to_tf32(kv.y); kv.z = to_tf32(kv.z); kv.w = to_tf32(kv.w);
            vv.x = to_tf32(vv.x); vv.y = to_tf32(vv.y); vv.z = to_tf32(vv.z); vv.w = to_tf32(vv.w);
            *(float4*)(Ks + row * KS_STRIDE + c4) = kv;
            *(float4*)(Vs + row * VS_STRIDE + c4) = vv;
        }
        __syncthreads();

        // S = Q K^T (16 x 64 per warp)
        float s[8][4];
#pragma unroll
        for (int ni = 0; ni < 8; ni++)
#pragma unroll
            for (int j = 0; j < 4; j++) s[ni][j] = 0.f;

#pragma unroll
        for (int d8 = 0; d8 < 8; d8++) {
#pragma unroll
            for (int ni = 0; ni < 8; ni++) {
                const float* p = Ks + (ni * 8 + g) * KS_STRIDE + d8 * 8 + t;
                mma_tf32(s[ni], qf[d8], fau(p[0]), fau(p[4]));
            }
        }

        // scale + mask + row max
        float mx0 = -1e30f, mx1 = -1e30f;
#pragma unroll
        for (int ni = 0; ni < 8; ni++) {
            int col = key0 + ni * 8 + 2 * t;
            s[ni][0] = (col     < lim0) ? s[ni][0] * 0.125f : -1e30f;
            s[ni][1] = (col + 1 < lim0) ? s[ni][1] * 0.125f : -1e30f;
            s[ni][2] = (col     < lim1) ? s[ni][2] * 0.125f : -1e30f;
            s[ni][3] = (col + 1 < lim1) ? s[ni][3] * 0.125f : -1e30f;
            mx0 = fmaxf(mx0, fmaxf(s[ni][0], s[ni][1]));
            mx1 = fmaxf(mx1, fmaxf(s[ni][2], s[ni][3]));
        }
        mx0 = fmaxf(mx0, __shfl_xor_sync(0xffffffffu, mx0, 1));
        mx0 = fmaxf(mx0, __shfl_xor_sync(0xffffffffu, mx0, 2));
        mx1 = fmaxf(mx1, __shfl_xor_sync(0xffffffffu, mx1, 1));
        mx1 = fmaxf(mx1, __shfl_xor_sync(0xffffffffu, mx1, 2));

        float mn0 = fmaxf(m0, mx0);
        float mn1 = fmaxf(m1, mx1);
        float sc0 = __expf(m0 - mn0);
        float sc1 = __expf(m1 - mn1);
        m0 = mn0; m1 = mn1;

        float rs0 = 0.f, rs1 = 0.f;
#pragma unroll
        for (int ni = 0; ni < 8; ni++) {
            float p0 = __expf(s[ni][0] - mn0);
            float p1 = __expf(s[ni][1] - mn0);
            float p2 = __expf(s[ni][2] - mn1);
            float p3 = __expf(s[ni][3] - mn1);
            rs0 += p0 + p1;
            rs1 += p2 + p3;
            *(float2*)(Ps + prow * KS_STRIDE + ni * 8 + 2 * t) =
                make_float2(to_tf32(p0), to_tf32(p1));
            *(float2*)(Ps + (prow + 8) * KS_STRIDE + ni * 8 + 2 * t) =
                make_float2(to_tf32(p2), to_tf32(p3));
        }
        rs0 += __shfl_xor_sync(0xffffffffu, rs0, 1);
        rs0 += __shfl_xor_sync(0xffffffffu, rs0, 2);
        rs1 += __shfl_xor_sync(0xffffffffu, rs1, 1);
        rs1 += __shfl_xor_sync(0xffffffffu, rs1, 2);
        l0 = l0 * sc0 + rs0;
        l1 = l1 * sc1 + rs1;

#pragma unroll
        for (int d8 = 0; d8 < 8; d8++) {
            o[d8][0] *= sc0; o[d8][1] *= sc0;
            o[d8][2] *= sc1; o[d8][3] *= sc1;
        }
        __syncwarp();

        // O += P V  (P is warp-private in Ps)
#pragma unroll
        for (int kk = 0; kk < 8; kk++) {
            uint32_t af[4];
            const float* pp = Ps + prow * KS_STRIDE + kk * 8 + t;
            af[0] = fau(pp[0]);
            af[1] = fau(pp[8 * KS_STRIDE]);
            af[2] = fau(pp[4]);
            af[3] = fau(pp[8 * KS_STRIDE + 4]);
#pragma unroll
            for (int d8 = 0; d8 < 8; d8++) {
                const float* pv = Vs + (kk * 8 + t) * VS_STRIDE + d8 * 8 + g;
                mma_tf32(o[d8], af, fau(pv[0]), fau(pv[4 * VS_STRIDE]));
            }
        }
        __syncthreads();
    }

    // write O / l  to g_att[token, h*64 + d]
    float il0 = 1.f / l0;
    float il1 = 1.f / l1;
    int r0 = q0 + prow;
    int r1 = r0 + 8;
#pragma unroll
    for (int d8 = 0; d8 < 8; d8++) {
        int col = hoff + d8 * 8 + 2 * t;
        if (r0 < TOTAL_N)
            *(float2*)(g_att + (rowbase + r0) * DMODEL + col) =
                make_float2(o[d8][0] * il0, o[d8][1] * il0);
        if (r1 < TOTAL_N)
            *(float2*)(g_att + (rowbase + r1) * DMODEL + col) =
                make_float2(o[d8][2] * il1, o[d8][3] * il1);
    }
}

// ---------------------------------------------------------------------------
// launch
// ---------------------------------------------------------------------------
extern "C" void kernel_launch(void* const* d_in, const int* in_sizes, int n_in,
                              void* d_out, int out_size) {
    (void)in_sizes; (void)n_in; (void)out_size;
    const float* x      = (const float*)d_in[0];
    const float* qkv_w  = (const float*)d_in[1];
    const float* qkv_b  = (const float*)d_in[2];
    const float* proj_w = (const float*)d_in[3];
    const float* proj_b = (const float*)d_in[4];
    float* out = (float*)d_out;

    // QKV: [21824, 2304]
    {
        dim3 grid((3 * DMODEL) / 128, (MTOK + 127) / 128);
        gemm_qkv_kernel<<<grid, 256>>>(x, qkv_w, qkv_b);
    }
    // attention
    {
        const int smem = (2 * 64 * KS_STRIDE + 64 * VS_STRIDE) * 4;  // 53248 B
        cudaFuncSetAttribute(attn_kernel, cudaFuncAttributeMaxDynamicSharedMemorySize, smem);
        dim3 grid((TOTAL_N + 63) / 64, NHEADS, BATCH);
        attn_kernel<<<grid, 128, smem>>>();
    }
    // proj: [21824, 768]
    {
        dim3 grid(DMODEL / 128, (MTOK + 127) / 128);
        gemm_proj_kernel<<<grid, 256>>>(proj_w, proj_b, out);
    }
}

// round 7
// speedup vs baseline: 1.6851x; 1.6851x over previous
#include <cuda_runtime.h>
#include <cstdint>

// Problem constants
#define TOTAL_N 341
#define BATCH   64
#define DMODEL  768
#define NHEADS  12
#define HDIM    64
#define MTOK    (BATCH * TOTAL_N)   // 21824

// Scratch (device globals: allocation-free)
__device__ __align__(1024) float g_qkv [(size_t)MTOK * 3 * DMODEL];   // [M, 2304]
__device__ __align__(1024) float g_att [(size_t)MTOK * DMODEL];       // [M, 768]
__device__ __align__(1024) float g_xr  [(size_t)MTOK * DMODEL];       // RNA-rounded x
__device__ __align__(1024) float g_wqkv[(size_t)3 * DMODEL * DMODEL]; // RNA-rounded qkv_w
__device__ __align__(1024) float g_wproj[(size_t)DMODEL * DMODEL];    // RNA-rounded proj_w

// ---------------------------------------------------------------------------
// helpers
// ---------------------------------------------------------------------------
__device__ __forceinline__ float to_tf32(float x) {
    uint32_t y;
    asm("cvt.rna.tf32.f32 %0, %1;" : "=r"(y) : "f"(x));
    return __uint_as_float(y);
}

__device__ __forceinline__ uint32_t fau(float x) { return __float_as_uint(x); }

__device__ __forceinline__ void mma_tf32(float* c, const uint32_t* a, uint32_t b0, uint32_t b1) {
    asm volatile(
        "mma.sync.aligned.m16n8k8.row.col.f32.tf32.tf32.f32 "
        "{%0,%1,%2,%3}, {%4,%5,%6,%7}, {%8,%9}, {%0,%1,%2,%3};\n"
        : "+f"(c[0]), "+f"(c[1]), "+f"(c[2]), "+f"(c[3])
        : "r"(a[0]), "r"(a[1]), "r"(a[2]), "r"(a[3]), "r"(b0), "r"(b1));
}

__device__ __forceinline__ int limit_of(int q) {
    if (q == 0)  return 341;
    if (q < 5)   return 5;
    if (q < 21)  return 21;
    if (q < 85)  return 85;
    return 341;
}

__device__ __forceinline__ void cp16(uint32_t dst, const float* src, int sz) {
    asm volatile("cp.async.cg.shared.global [%0], [%1], 16, %2;\n"
                 :: "r"(dst), "l"(src), "r"(sz));
}

__device__ __forceinline__ uint32_t smem_u32(const void* p) {
    return (uint32_t)__cvta_generic_to_shared(p);
}

// ---------------------------------------------------------------------------
// RNA pre-round kernel (fp32 -> tf32-valued fp32)
// ---------------------------------------------------------------------------
__global__ __launch_bounds__(256) void round_kernel(const float* __restrict__ s,
                                                    float* __restrict__ d, int n) {
    int i = (blockIdx.x * blockDim.x + threadIdx.x) * 4;
    if (i < n) {
        float4 v = *(const float4*)(s + i);
        v.x = to_tf32(v.x); v.y = to_tf32(v.y); v.z = to_tf32(v.z); v.w = to_tf32(v.w);
        *(float4*)(d + i) = v;
    }
}

// ---------------------------------------------------------------------------
// mma.sync tf32 GEMM v2: C[M,NG] = A[M,768] @ W[NG,768]^T + bias[NG]
// CTA tile 128(M) x 256(N) x 32(K). 8 warps (2 x 4), warp tile 64x64.
// 3-stage cp.async pipeline. smem row stride 36 floats (conflict-free).
// ---------------------------------------------------------------------------
#define TK     32
#define RS     36                                  // row stride in floats
#define A_ROWS 128
#define B_ROWS 256
#define STG_FL ((A_ROWS + B_ROWS) * RS)            // floats per stage: 13824
#define STG_B  (STG_FL * 4)                        // 55296 bytes
#define NSTG   3
#define GEMM_SMEM (NSTG * STG_B)                   // 165888 bytes

template <int NG>
__global__ __launch_bounds__(256) void gemm_v2(const float* __restrict__ A,
                                               const float* __restrict__ W,
                                               const float* __restrict__ bias,
                                               float* __restrict__ C, int M) {
    extern __shared__ float sm[];

    const int tid  = threadIdx.x;
    const int lane = tid & 31;
    const int warp = tid >> 5;
    const int g    = lane >> 2;   // 0..7
    const int t    = lane & 3;    // 0..3
    const int wm   = warp >> 2;   // 0..1  (M half)
    const int wn   = warp & 3;    // 0..3  (N quarter)
    const int bm   = blockIdx.y * A_ROWS;
    const int bn   = blockIdx.x * B_ROWS;

    const uint32_t smb = smem_u32(sm);

    // issue one stage of cp.async: A tile 128x32, B tile 256x32
    auto issue = [&](int kb, int s) {
        uint32_t base = smb + s * STG_B;
        // A: 128 rows x 8 chunks = 1024 cp16 -> 4 per thread
#pragma unroll
        for (int i = 0; i < 4; i++) {
            int idx = tid + i * 256;
            int row = idx >> 3, c = idx & 7;
            int gr = bm + row;
            int ok = gr < M;
            const float* src = A + (size_t)(ok ? gr : 0) * DMODEL + kb * TK + c * 4;
            cp16(base + (row * RS + c * 4) * 4, src, ok ? 16 : 0);
        }
        // B: 256 rows x 8 chunks = 2048 cp16 -> 8 per thread
        uint32_t bbase = base + A_ROWS * RS * 4;
#pragma unroll
        for (int i = 0; i < 8; i++) {
            int idx = tid + i * 256;
            int row = idx >> 3, c = idx & 7;
            const float* src = W + (size_t)(bn + row) * DMODEL + kb * TK + c * 4;
            cp16(bbase + (row * RS + c * 4) * 4, src, 16);
        }
    };

    float acc[4][8][4];
#pragma unroll
    for (int mi = 0; mi < 4; mi++)
#pragma unroll
        for (int ni = 0; ni < 8; ni++)
#pragma unroll
            for (int j = 0; j < 4; j++) acc[mi][ni][j] = 0.f;

    const int KT = DMODEL / TK;  // 24

    issue(0, 0);
    asm volatile("cp.async.commit_group;" ::: "memory");
    issue(1, 1);
    asm volatile("cp.async.commit_group;" ::: "memory");

    for (int kb = 0; kb < KT; kb++) {
        asm volatile("cp.async.wait_group 1;" ::: "memory");
        __syncthreads();

        const int s = kb % NSTG;
        const float* As = sm + s * STG_FL;
        const float* Bs = As + A_ROWS * RS;

#pragma unroll
        for (int ks = 0; ks < 4; ks++) {
            const int k0 = ks * 8;
            uint32_t af[4][4];
#pragma unroll
            for (int mi = 0; mi < 4; mi++) {
                const float* p = As + (wm * 64 + mi * 16 + g) * RS + k0 + t;
                af[mi][0] = fau(p[0]);
                af[mi][1] = fau(p[8 * RS]);
                af[mi][2] = fau(p[4]);
                af[mi][3] = fau(p[8 * RS + 4]);
            }
#pragma unroll
            for (int ni = 0; ni < 8; ni++) {
                const float* p = Bs + (wn * 64 + ni * 8 + g) * RS + k0 + t;
                uint32_t b0 = fau(p[0]);
                uint32_t b1 = fau(p[4]);
#pragma unroll
                for (int mi = 0; mi < 4; mi++) mma_tf32(acc[mi][ni], af[mi], b0, b1);
            }
        }
        __syncthreads();

        if (kb + 2 < KT) issue(kb + 2, (kb + 2) % NSTG);
        asm volatile("cp.async.commit_group;" ::: "memory");
    }

    // epilogue: + bias, store
#pragma unroll
    for (int mi = 0; mi < 4; mi++) {
        int r0 = bm + wm * 64 + mi * 16 + g;
        int r1 = r0 + 8;
#pragma unroll
        for (int ni = 0; ni < 8; ni++) {
            int col = bn + wn * 64 + ni * 8 + 2 * t;
            float b0 = bias[col], b1 = bias[col + 1];
            if (r0 < M) {
                float2 v = make_float2(acc[mi][ni][0] + b0, acc[mi][ni][1] + b1);
                *(float2*)(C + (size_t)r0 * NG + col) = v;
            }
            if (r1 < M) {
                float2 v = make_float2(acc[mi][ni][2] + b0, acc[mi][ni][3] + b1);
                *(float2*)(C + (size_t)r1 * NG + col) = v;
            }
        }
    }
}

// ---------------------------------------------------------------------------
// Fused flash attention: one CTA = (q-tile of 64 rows, head, batch)
// 4 warps x 16 q-rows. tf32 mma for S=Q K^T and O += P V.
// NOTE: no key-tile skipping — every 64-row q-tile contains at least one row
// with limit 341 (tile 0 has CLS, tile 1 has rows >= 85), mask handles rest.
// ---------------------------------------------------------------------------
#define KS_STRIDE 68
#define VS_STRIDE 72

__global__ __launch_bounds__(128) void attn_kernel() {
    extern __shared__ float sm[];
    float* Ks = sm;
    float* Ps = sm + 64 * KS_STRIDE;
    float* Vs = sm + 2 * 64 * KS_STRIDE;

    const int tid  = threadIdx.x;
    const int lane = tid & 31;
    const int warp = tid >> 5;
    const int g    = lane >> 2;
    const int t    = lane & 3;

    const int q0 = blockIdx.x * 64;
    const int h  = blockIdx.y;
    const int b  = blockIdx.z;
    const size_t rowbase = (size_t)b * TOTAL_N;
    const int hoff = h * HDIM;

#pragma unroll
    for (int i = 0; i < 8; i++) {
        int idx = tid + i * 128;
        int row = idx >> 4;
        int c4  = (idx & 15) << 2;
        float4 v = make_float4(0.f, 0.f, 0.f, 0.f);
        int qi = q0 + row;
        if (qi < TOTAL_N) v = *(const float4*)(g_qkv + (rowbase + qi) * 2304 + hoff + c4);
        v.x = to_tf32(v.x); v.y = to_tf32(v.y); v.z = to_tf32(v.z); v.w = to_tf32(v.w);
        *(float4*)(Ps + row * KS_STRIDE + c4) = v;
    }
    __syncthreads();

    const int prow = warp * 16 + g;
    uint32_t qf[8][4];
#pragma unroll
    for (int d8 = 0; d8 < 8; d8++) {
        const float* p = Ps + prow * KS_STRIDE + d8 * 8 + t;
        qf[d8][0] = fau(p[0]);
        qf[d8][1] = fau(p[8 * KS_STRIDE]);
        qf[d8][2] = fau(p[4]);
        qf[d8][3] = fau(p[8 * KS_STRIDE + 4]);
    }
    __syncthreads();

    float o[8][4];
#pragma unroll
    for (int d8 = 0; d8 < 8; d8++)
#pragma unroll
        for (int j = 0; j < 4; j++) o[d8][j] = 0.f;

    float m0 = -1e30f, m1 = -1e30f, l0 = 0.f, l1 = 0.f;
    const int lim0 = limit_of(q0 + prow);
    const int lim1 = limit_of(q0 + prow + 8);

    for (int kt = 0; kt < 6; kt++) {
        int key0 = kt * 64;
#pragma unroll
        for (int i = 0; i < 8; i++) {
            int idx = tid + i * 128;
            int row = idx >> 4;
            int c4  = (idx & 15) << 2;
            float4 kv = make_float4(0.f, 0.f, 0.f, 0.f);
            float4 vv = make_float4(0.f, 0.f, 0.f, 0.f);
            int key = key0 + row;
            if (key < TOTAL_N) {
                const float* base = g_qkv + (rowbase + key) * 2304 + hoff;
                kv = *(const float4*)(base + DMODEL + c4);
                vv = *(const float4*)(base + 2 * DMODEL + c4);
            }
            kv.x = to_tf32(kv.x); kv.y = to_tf32(kv.y); kv.z = to_tf32(kv.z); kv.w = to_tf32(kv.w);
            vv.x = to_tf32(vv.x); vv.y = to_tf32(vv.y); vv.z = to_tf32(vv.z); vv.w = to_tf32(vv.w);
            *(float4*)(Ks + row * KS_STRIDE + c4) = kv;
            *(float4*)(Vs + row * VS_STRIDE + c4) = vv;
        }
        __syncthreads();

        float s[8][4];
#pragma unroll
        for (int ni = 0; ni < 8; ni++)
#pragma unroll
            for (int j = 0; j < 4; j++) s[ni][j] = 0.f;

#pragma unroll
        for (int d8 = 0; d8 < 8; d8++) {
#pragma unroll
            for (int ni = 0; ni < 8; ni++) {
                const float* p = Ks + (ni * 8 + g) * KS_STRIDE + d8 * 8 + t;
                mma_tf32(s[ni], qf[d8], fau(p[0]), fau(p[4]));
            }
        }

        float mx0 = -1e30f, mx1 = -1e30f;
#pragma unroll
        for (int ni = 0; ni < 8; ni++) {
            int col = key0 + ni * 8 + 2 * t;
            s[ni][0] = (col     < lim0) ? s[ni][0] * 0.125f : -1e30f;
            s[ni][1] = (col + 1 < lim0) ? s[ni][1] * 0.125f : -1e30f;
            s[ni][2] = (col     < lim1) ? s[ni][2] * 0.125f : -1e30f;
            s[ni][3] = (col + 1 < lim1) ? s[ni][3] * 0.125f : -1e30f;
            mx0 = fmaxf(mx0, fmaxf(s[ni][0], s[ni][1]));
            mx1 = fmaxf(mx1, fmaxf(s[ni][2], s[ni][3]));
        }
        mx0 = fmaxf(mx0, __shfl_xor_sync(0xffffffffu, mx0, 1));
        mx0 = fmaxf(mx0, __shfl_xor_sync(0xffffffffu, mx0, 2));
        mx1 = fmaxf(mx1, __shfl_xor_sync(0xffffffffu, mx1, 1));
        mx1 = fmaxf(mx1, __shfl_xor_sync(0xffffffffu, mx1, 2));

        float mn0 = fmaxf(m0, mx0);
        float mn1 = fmaxf(m1, mx1);
        float sc0 = __expf(m0 - mn0);
        float sc1 = __expf(m1 - mn1);
        m0 = mn0; m1 = mn1;

        float rs0 = 0.f, rs1 = 0.f;
#pragma unroll
        for (int ni = 0; ni < 8; ni++) {
            float p0 = __expf(s[ni][0] - mn0);
            float p1 = __expf(s[ni][1] - mn0);
            float p2 = __expf(s[ni][2] - mn1);
            float p3 = __expf(s[ni][3] - mn1);
            rs0 += p0 + p1;
            rs1 += p2 + p3;
            *(float2*)(Ps + prow * KS_STRIDE + ni * 8 + 2 * t) =
                make_float2(to_tf32(p0), to_tf32(p1));
            *(float2*)(Ps + (prow + 8) * KS_STRIDE + ni * 8 + 2 * t) =
                make_float2(to_tf32(p2), to_tf32(p3));
        }
        rs0 += __shfl_xor_sync(0xffffffffu, rs0, 1);
        rs0 += __shfl_xor_sync(0xffffffffu, rs0, 2);
        rs1 += __shfl_xor_sync(0xffffffffu, rs1, 1);
        rs1 += __shfl_xor_sync(0xffffffffu, rs1, 2);
        l0 = l0 * sc0 + rs0;
        l1 = l1 * sc1 + rs1;

#pragma unroll
        for (int d8 = 0; d8 < 8; d8++) {
            o[d8][0] *= sc0; o[d8][1] *= sc0;
            o[d8][2] *= sc1; o[d8][3] *= sc1;
        }
        __syncwarp();

#pragma unroll
        for (int kk = 0; kk < 8; kk++) {
            uint32_t af[4];
            const float* pp = Ps + prow * KS_STRIDE + kk * 8 + t;
            af[0] = fau(pp[0]);
            af[1] = fau(pp[8 * KS_STRIDE]);
            af[2] = fau(pp[4]);
            af[3] = fau(pp[8 * KS_STRIDE + 4]);
#pragma unroll
            for (int d8 = 0; d8 < 8; d8++) {
                const float* pv = Vs + (kk * 8 + t) * VS_STRIDE + d8 * 8 + g;
                mma_tf32(o[d8], af, fau(pv[0]), fau(pv[4 * VS_STRIDE]));
            }
        }
        __syncthreads();
    }

    float il0 = 1.f / l0;
    float il1 = 1.f / l1;
    int r0 = q0 + prow;
    int r1 = r0 + 8;
#pragma unroll
    for (int d8 = 0; d8 < 8; d8++) {
        int col = hoff + d8 * 8 + 2 * t;
        if (r0 < TOTAL_N)
            *(float2*)(g_att + (rowbase + r0) * DMODEL + col) =
                make_float2(to_tf32(o[d8][0] * il0), to_tf32(o[d8][1] * il0));
        if (r1 < TOTAL_N)
            *(float2*)(g_att + (rowbase + r1) * DMODEL + col) =
                make_float2(to_tf32(o[d8][2] * il1), to_tf32(o[d8][3] * il1));
    }
}

// ---------------------------------------------------------------------------
// launch
// ---------------------------------------------------------------------------
extern "C" void kernel_launch(void* const* d_in, const int* in_sizes, int n_in,
                              void* d_out, int out_size) {
    (void)in_sizes; (void)n_in; (void)out_size;
    const float* x      = (const float*)d_in[0];
    const float* qkv_w  = (const float*)d_in[1];
    const float* qkv_b  = (const float*)d_in[2];
    const float* proj_w = (const float*)d_in[3];
    const float* proj_b = (const float*)d_in[4];
    float* out = (float*)d_out;

    float *xr, *wq, *wp, *qkv, *att;
    cudaGetSymbolAddress((void**)&xr,  g_xr);
    cudaGetSymbolAddress((void**)&wq,  g_wqkv);
    cudaGetSymbolAddress((void**)&wp,  g_wproj);
    cudaGetSymbolAddress((void**)&qkv, g_qkv);
    cudaGetSymbolAddress((void**)&att, g_att);

    // RNA pre-round inputs (so cp.async-staged bits are exact tf32 values)
    {
        int n1 = MTOK * DMODEL;
        round_kernel<<<(n1 / 4 + 255) / 256, 256>>>(x, xr, n1);
        int n2 = 3 * DMODEL * DMODEL;
        round_kernel<<<(n2 / 4 + 255) / 256, 256>>>(qkv_w, wq, n2);
        int n3 = DMODEL * DMODEL;
        round_kernel<<<(n3 / 4 + 255) / 256, 256>>>(proj_w, wp, n3);
    }

    // QKV GEMM: [21824, 2304]
    {
        cudaFuncSetAttribute(gemm_v2<3 * DMODEL>,
                             cudaFuncAttributeMaxDynamicSharedMemorySize, GEMM_SMEM);
        dim3 grid((3 * DMODEL) / B_ROWS, (MTOK + A_ROWS - 1) / A_ROWS);  // (9, 171)
        gemm_v2<3 * DMODEL><<<grid, 256, GEMM_SMEM>>>(xr, wq, qkv_b, qkv, MTOK);
    }
    // attention
    {
        const int smem = (2 * 64 * KS_STRIDE + 64 * VS_STRIDE) * 4;
        cudaFuncSetAttribute(attn_kernel, cudaFuncAttributeMaxDynamicSharedMemorySize, smem);
        dim3 grid((TOTAL_N + 63) / 64, NHEADS, BATCH);
        attn_kernel<<<grid, 128, smem>>>();
    }
    // proj GEMM: [21824, 768]
    {
        cudaFuncSetAttribute(gemm_v2<DMODEL>,
                             cudaFuncAttributeMaxDynamicSharedMemorySize, GEMM_SMEM);
        dim3 grid(DMODEL / B_ROWS, (MTOK + A_ROWS - 1) / A_ROWS);  // (3, 171)
        gemm_v2<DMODEL><<<grid, 256, GEMM_SMEM>>>(att, wp, proj_b, out, MTOK);
    }
}